// round 15
// baseline (speedup 1.0000x reference)
#include <cuda_runtime.h>
#include <cuda_bf16.h>
#include <cuda_fp16.h>
#include <math.h>
#include <stdint.h>

#define BB 4
#define NN 8192
#define KK 24
#define DP 32
#define DM 64
#define PE 60
#define DK (DM*KK)        // 1536
#define BN (BB*NN)        // 32768
#define RR (BN*KK)        // 786432

// Scratch (allocation-free rule: __device__ globals)
__device__ float g_x[BN*DM];                  // fc1 output
__device__ int   g_knn[RR];                   // knn indices
__device__ __half g_pre[(size_t)RR*DM];       // fp16(q - kf + pos_enc)
__device__ __half g_vpe[(size_t)RR*DM];       // fp16(vf + pos_enc)
__device__ __half g_logit[(size_t)RR*DM];     // fp16 attn logits (pre-softmax)
__device__ __half g_wa[DK*DK];                // fp16 Wa
__device__ __half g_w1h[DM*DM];               // fp16 Wd1 [n=64][k=64], k 60..63 zero
__device__ __half g_w2h[DM*DM];               // fp16 Wd2 [n=64][k=64]

// ================= helpers (sm_80-compatible only) =================
__device__ __forceinline__ uint32_t smem_u32(const void* p) {
    uint32_t a;
    asm("{ .reg .u64 t; cvta.to.shared.u64 t, %1; cvt.u32.u64 %0, t; }" : "=r"(a) : "l"(p));
    return a;
}
#define SWZ(x) ((x) ^ (((x) >> 3) & 0x70))
__device__ __forceinline__ void cp16(uint32_t s, const void* g) {
    asm volatile("cp.async.cg.shared.global [%0], [%1], 16;" :: "r"(s), "l"(g));
}
__device__ __forceinline__ void ldsm4(uint32_t& r0, uint32_t& r1, uint32_t& r2, uint32_t& r3,
                                      uint32_t addr) {
    asm volatile("ldmatrix.sync.aligned.m8n8.x4.shared.b16 {%0,%1,%2,%3}, [%4];"
                 : "=r"(r0), "=r"(r1), "=r"(r2), "=r"(r3) : "r"(addr));
}
__device__ __forceinline__ void mma_fp16(float* c, const uint32_t* a, const uint32_t* b) {
    asm volatile("mma.sync.aligned.m16n8k16.row.col.f32.f16.f16.f32 "
                 "{%0,%1,%2,%3}, {%4,%5,%6,%7}, {%8,%9}, {%0,%1,%2,%3};"
                 : "+f"(c[0]), "+f"(c[1]), "+f"(c[2]), "+f"(c[3])
                 : "r"(a[0]), "r"(a[1]), "r"(a[2]), "r"(a[3]), "r"(b[0]), "r"(b[1]));
}
__device__ __forceinline__ uint32_t packh2(float a, float b) {
    __half2 h = __floats2half2_rn(a, b);
    return *(uint32_t*)&h;
}

// ================= prep: fc1 + Wa->fp16 + Wd transpose (one launch) =================
#define FC1_BLKS (BN*DM/256)       // 8192
#define WA_BLKS  (DK*DK/256)       // 9216
#define WD_BLKS  ((2*DM*DM+255)/256) // 32
__global__ void prep_kernel(const float* __restrict__ feat,
                            const float* __restrict__ W1,
                            const float* __restrict__ b1,
                            const float* __restrict__ Wa,
                            const float* __restrict__ Wd1,
                            const float* __restrict__ Wd2) {
    int bid = blockIdx.x;
    if (bid < FC1_BLKS) {
        int t = bid * 256 + threadIdx.x;
        int p = t >> 6, d = t & 63;
        const float* f = feat + (size_t)p * DP;
        const float* w = W1 + d * DP;
        float s = b1[d];
#pragma unroll
        for (int i = 0; i < DP; i++) s = fmaf(f[i], w[i], s);
        g_x[t] = s;
    } else if (bid < FC1_BLKS + WA_BLKS) {
        int t = (bid - FC1_BLKS) * 256 + threadIdx.x;
        g_wa[t] = __float2half(Wa[t]);
    } else {
        int t = (bid - FC1_BLKS - WA_BLKS) * 256 + threadIdx.x;
        if (t < DM*DM) {
            int n = t >> 6, k = t & 63;
            g_w1h[t] = __float2half(k < PE ? Wd1[n*PE + k] : 0.0f);
        } else if (t < 2*DM*DM) {
            int u = t - DM*DM;
            g_w2h[u] = __float2half(Wd2[u]);
        }
    }
}

// ================= KNN: resident point cloud, warp-per-query top-24 =================
// Whole batch xyz (8192 x float4 = 128KB) resident in smem; one barrier total.
// 32-lane sorted list; lanes 0..23 = answer, 24..31 = overflow (stale-threshold safe).
#define KQW 32
#define KNN_SMEM (NN * 16)
#define FULLM 0xFFFFFFFFu
__global__ __launch_bounds__(1024) void knn_kernel(const float* __restrict__ xyz) {
    extern __shared__ float4 s4[];
    const int tid = threadIdx.x;
    const int warp = tid >> 5, lane = tid & 31;
    const int b = blockIdx.y;
    const int q = blockIdx.x * KQW + warp;
    const float* base = xyz + (size_t)b * NN * 3;

    for (int t = tid; t < NN; t += 1024) {
        float x = base[3*t], y = base[3*t+1], z = base[3*t+2];
        s4[t] = make_float4(x, y, z, x*x + y*y + z*z);
    }
    __syncthreads();

    const float qx = base[3*q], qy = base[3*q+1], qz = base[3*q+2];
    const float qs = qx*qx + qy*qy + qz*qz;

    float kd = 3.4e38f;          // per-lane list entry
    int   ki = 0x7fffffff;
    float wd = 3.4e38f;          // cached lane-23 worst (stale = conservative)

    for (int jj = 0; jj < NN; jj += 64) {
        float4 c1 = s4[jj + lane];
        float4 c2 = s4[jj + 32 + lane];
        float d1 = (qs + c1.w) - 2.0f * (qx*c1.x + qy*c1.y + qz*c1.z);
        float d2 = (qs + c2.w) - 2.0f * (qx*c2.x + qy*c2.y + qz*c2.z);
        int i1 = jj + lane;
        int i2 = i1 + 32;
        unsigned m1 = __ballot_sync(FULLM, d1 <= wd);
        unsigned m2 = __ballot_sync(FULLM, d2 <= wd);
        if ((m1 | m2) == 0) continue;
#pragma unroll
        for (int half = 0; half < 2; half++) {
            unsigned m = half ? m2 : m1;
            float dcur = half ? d2 : d1;
            int icur = half ? i2 : i1;
            while (m) {
                int src = __ffs(m) - 1; m &= m - 1;
                float cd = __shfl_sync(FULLM, dcur, src);
                int   ci = __shfl_sync(FULLM, icur, src);
                float ud = __shfl_up_sync(FULLM, kd, 1);
                int   ui = __shfl_up_sync(FULLM, ki, 1);
                bool self_gt = (kd > cd) || (kd == cd && ki > ci);
                bool prev_gt = (lane != 0) && ((ud > cd) || (ud == cd && ui > ci));
                if (self_gt) {
                    kd = prev_gt ? ud : cd;
                    ki = prev_gt ? ui : ci;
                }
            }
        }
        wd = __shfl_sync(FULLM, kd, 23);   // refresh worst once per group
    }
    if (lane < KK) g_knn[((size_t)b * NN + q) * KK + lane] = ki;
}

// ================= posenc: b2b tensor-core MMA (128 rows, 256 thr) =================
#define POSB 128
__global__ __launch_bounds__(256) void posenc_kernel(const float* __restrict__ xyz,
                                                     const float* __restrict__ bd1,
                                                     const float* __restrict__ bd2) {
    __shared__ __align__(16) char w1s[8192];
    __shared__ __align__(16) char w2s[8192];
    __shared__ __align__(16) char pes[POSB*128];
    __shared__ float dxs[POSB*3];
    __shared__ float om[16];
    __shared__ float b1s[DM], b2s[DM];
    __shared__ int knn_s[POSB];

    const int tid = threadIdx.x;
    const int lane = tid & 31, warp = tid >> 5;
    const int rbase = blockIdx.x * POSB;
    const uint32_t w1a = smem_u32(w1s), w2a = smem_u32(w2s), pea = smem_u32(pes);

    for (int gi = tid; gi < 512; gi += 256) {
        int row = gi >> 3, seg = gi & 7;
        uint32_t so = SWZ((uint32_t)(row*128 + seg*16));
        cp16(w1a + so, g_w1h + row*64 + seg*8);
        cp16(w2a + so, g_w2h + row*64 + seg*8);
    }
    asm volatile("cp.async.commit_group;" ::: "memory");
    if (tid < 10) om[tid] = exp2f(-(float)tid * 1.3287712379549449f);  // 10000^(-tid/10)
    if (tid < DM) { b1s[tid] = bd1[tid]; b2s[tid] = bd2[tid]; }
    if (tid < POSB) {
        int row = rbase + tid;
        int bn = row / KK;
        int b = bn / NN, n = bn % NN;
        int idx = g_knn[row];
        knn_s[tid] = idx;
        const float* xb = xyz + (size_t)b * NN * 3;
        dxs[tid*3+0] = xb[3*n+0] - xb[3*idx+0];
        dxs[tid*3+1] = xb[3*n+1] - xb[3*idx+1];
        dxs[tid*3+2] = xb[3*n+2] - xb[3*idx+2];
    }
    asm volatile("cp.async.wait_group 0;" ::: "memory");
    __syncthreads();

    for (int p = tid; p < POSB*30; p += 256) {
        int r = p / 30, j2 = p % 30;
        float v[2];
#pragma unroll
        for (int u = 0; u < 2; u++) {
            int j = j2*2 + u;
            int axis = j / 20, tt = j % 20;
            int oi = (tt < 10) ? tt : tt - 10;
            float ang = dxs[r*3 + axis] * om[oi];
            v[u] = (tt < 10) ? __sinf(ang) : __cosf(ang);
        }
        *(uint32_t*)(pes + SWZ((uint32_t)(r*128 + j2*4))) = packh2(v[0], v[1]);
    }
    for (int r = tid; r < POSB; r += 256) {
        *(uint32_t*)(pes + SWZ((uint32_t)(r*128 + 120))) = 0;
        *(uint32_t*)(pes + SWZ((uint32_t)(r*128 + 124))) = 0;
    }
    __syncthreads();

    const int g = lane >> 2, tg = lane & 3;
    const int arow = lane & 15;
    const int akx  = (lane >> 4) << 4;
    const int brow = (lane & 7) + ((lane >> 4) << 3);
    const int bkx  = ((lane >> 3) & 1) << 4;
    const int wbase = warp * 16;

    float acc1[8][4];
#pragma unroll
    for (int j = 0; j < 8; j++)
#pragma unroll
        for (int i = 0; i < 4; i++) acc1[j][i] = 0.0f;
#pragma unroll
    for (int kt = 0; kt < 4; kt++) {
        int kb = kt * 32;
        uint32_t af[4];
        {
            int row = wbase + arow;
            uint32_t off = (uint32_t)row*128 + (uint32_t)((kb + akx) ^ ((row & 7) << 4));
            ldsm4(af[0], af[1], af[2], af[3], pea + off);
        }
        uint32_t bf[8][2];
#pragma unroll
        for (int nj = 0; nj < 4; nj++) {
            int row = nj*16 + brow;
            uint32_t off = (uint32_t)row*128 + (uint32_t)((kb + bkx) ^ ((row & 7) << 4));
            ldsm4(bf[nj*2][0], bf[nj*2][1], bf[nj*2+1][0], bf[nj*2+1][1], w1a + off);
        }
#pragma unroll
        for (int j = 0; j < 8; j++) mma_fp16(acc1[j], af, bf[j]);
    }

    uint32_t a2[4][4];
#pragma unroll
    for (int j = 0; j < 8; j++) {
        int c0 = 8*j + 2*tg;
        float h0 = fmaxf(acc1[j][0] + b1s[c0],   0.0f);
        float h1 = fmaxf(acc1[j][1] + b1s[c0+1], 0.0f);
        float h2 = fmaxf(acc1[j][2] + b1s[c0],   0.0f);
        float h3 = fmaxf(acc1[j][3] + b1s[c0+1], 0.0f);
        a2[j>>1][(j&1)*2 + 0] = packh2(h0, h1);
        a2[j>>1][(j&1)*2 + 1] = packh2(h2, h3);
    }

    float acc2[8][4];
#pragma unroll
    for (int j = 0; j < 8; j++)
#pragma unroll
        for (int i = 0; i < 4; i++) acc2[j][i] = 0.0f;
#pragma unroll
    for (int kt = 0; kt < 4; kt++) {
        int kb = kt * 32;
        uint32_t bf[8][2];
#pragma unroll
        for (int nj = 0; nj < 4; nj++) {
            int row = nj*16 + brow;
            uint32_t off = (uint32_t)row*128 + (uint32_t)((kb + bkx) ^ ((row & 7) << 4));
            ldsm4(bf[nj*2][0], bf[nj*2][1], bf[nj*2+1][0], bf[nj*2+1][1], w2a + off);
        }
#pragma unroll
        for (int j = 0; j < 8; j++) mma_fp16(acc2[j], a2[kt], bf[j]);
    }

#pragma unroll
    for (int rr = 0; rr < 2; rr++) {
        int lrow = wbase + g + rr*8;
        int row = rbase + lrow;
        int bn = row / KK;
        int b = bn / NN;
        int idx = knn_s[lrow];
        const float* qp = g_x + (size_t)bn * DM;
        const float* kp = g_x + ((size_t)b * NN + idx) * DM;
        __half* ph = g_pre + (size_t)row * DM;
        __half* vp = g_vpe + (size_t)row * DM;
#pragma unroll
        for (int j = 0; j < 8; j++) {
            int c0 = 8*j + 2*tg;
            float pos0 = acc2[j][rr*2+0] + b2s[c0];
            float pos1 = acc2[j][rr*2+1] + b2s[c0+1];
            float2 qv = *(const float2*)(qp + c0);
            float2 kf = *(const float2*)(kp + c0);
            *(uint32_t*)(ph + c0) = packh2(qv.x - kf.x + pos0, qv.y - kf.y + pos1);
            *(uint32_t*)(vp + c0) = packh2(kf.x + pos0, kf.y + pos1);
        }
    }
}

// ================= attention GEMM (R11 geometry, fp16 logit epilogue) =================
#define TM 128
#define TN 128
#define KC 64
#define NCH (DK/KC)          // 24
#define NSTG 3
#define STG_B 32768          // A 16K | B 16K
#define SMEM_GEMM (NSTG*STG_B)  // 98304

__global__ void __launch_bounds__(256, 2)
attn_gemm_mma(const float* __restrict__ ba) {
    extern __shared__ char smem[];
    const uint32_t sb = smem_u32(smem);
    const int tid = threadIdx.x;
    const int warp = tid >> 5, lane = tid & 31;
    const int bm = blockIdx.y * TM;
    const int bn = blockIdx.x * TN;
    const int wm = (warp >> 2) * 64;     // 0/64
    const int wn = (warp & 3) * 32;      // 0/32/64/96

    const __half* Ap = g_pre + (size_t)bm * DK;
    const __half* Bp = g_wa  + (size_t)bn * DK;

    auto load_chunk = [&](int c, int s) {
        int kt = c * KC;
        uint32_t st = sb + s * STG_B;
#pragma unroll
        for (int i = 0; i < 4; i++) {
            int u = tid + i * 256;
            int row = u >> 3, seg = u & 7;          // 128 rows x 8 x 16B
            uint32_t so = SWZ((uint32_t)(row * 128 + seg * 16));
            size_t go = (size_t)row * DK + kt + seg * 8;
            cp16(st + so,          Ap + go);
            cp16(st + 16384 + so,  Bp + go);
        }
        asm volatile("cp.async.commit_group;" ::: "memory");
    };

    const int arow = lane & 15;
    const int akx  = (lane >> 4) << 4;
    const int brow = (lane & 7) + ((lane >> 4) << 3);
    const int bkx  = ((lane >> 3) & 1) << 4;

    float acc[4][4][4];
#pragma unroll
    for (int a = 0; a < 4; a++)
#pragma unroll
        for (int b = 0; b < 4; b++)
#pragma unroll
            for (int c = 0; c < 4; c++) acc[a][b][c] = 0.0f;

    load_chunk(0, 0);
    load_chunk(1, 1);

    for (int c = 0; c < NCH; c++) {
        int s = c % NSTG;
        asm volatile("cp.async.wait_group 1;" ::: "memory");
        __syncthreads();
        if (c + 2 < NCH) load_chunk(c + 2, (c + 2) % NSTG);

        uint32_t st = sb + s * STG_B;
#pragma unroll
        for (int k16 = 0; k16 < 4; k16++) {
            int kb = k16 * 32;
            uint32_t af[4][4];
#pragma unroll
            for (int mi = 0; mi < 4; mi++) {
                int row = wm + mi * 16 + arow;
                uint32_t off = (uint32_t)row * 128 + (uint32_t)((kb + akx) ^ ((row & 7) << 4));
                ldsm4(af[mi][0], af[mi][1], af[mi][2], af[mi][3], st + off);
            }
            uint32_t bf[4][2];
#pragma unroll
            for (int nj = 0; nj < 2; nj++) {
                int row = wn + nj * 16 + brow;
                uint32_t off = (uint32_t)row * 128 + (uint32_t)((kb + bkx) ^ ((row & 7) << 4));
                ldsm4(bf[nj*2][0], bf[nj*2][1], bf[nj*2+1][0], bf[nj*2+1][1], st + 16384 + off);
            }
#pragma unroll
            for (int mi = 0; mi < 4; mi++)
#pragma unroll
                for (int ni = 0; ni < 4; ni++)
                    mma_fp16(acc[mi][ni], af[mi], bf[ni]);
        }
    }

    // epilogue: bias + fp16 logit store
    const int g = lane >> 2, tg = lane & 3;
#pragma unroll
    for (int mi = 0; mi < 4; mi++) {
        int r0 = bm + wm + mi * 16 + g;
        __half* o0 = g_logit + (size_t)r0 * DK;
        __half* o1 = g_logit + (size_t)(r0 + 8) * DK;
#pragma unroll
        for (int ni = 0; ni < 4; ni++) {
            int col = bn + wn + ni * 8 + tg * 2;
            float bv0 = __ldg(&ba[col]), bv1 = __ldg(&ba[col + 1]);
            *(uint32_t*)(o0 + col) = packh2(acc[mi][ni][0] + bv0, acc[mi][ni][1] + bv1);
            *(uint32_t*)(o1 + col) = packh2(acc[mi][ni][2] + bv0, acc[mi][ni][3] + bv1);
        }
    }
}

// ================= softmax + weighted sum + fc2 + residual (fp16 logits in) =================
__global__ __launch_bounds__(256) void softmax_out(const float* __restrict__ W2,
                                                   const float* __restrict__ b2,
                                                   float* __restrict__ out_res,
                                                   float* __restrict__ out_attn) {
    __shared__ float w2_s[DM][DM];     // transposed: w2_s[e][d]
    __shared__ float res_s[8][DM];
    int tid = threadIdx.x;
    int slot = tid >> 5, d2 = tid & 31;
    int d = d2 * 2;
    for (int t = tid; t < DM*DM; t += 256) { int dd = t / DM, e = t % DM; w2_s[e][dd] = W2[t]; }
    __syncthreads();

    int bn = blockIdx.x * 8 + slot;
    const __half* lp = g_logit + (size_t)bn * KK * DM + d;
    const __half* vp = g_vpe + (size_t)bn * KK * DM + d;
    float* ao = out_attn + (size_t)bn * KK * DM + d;

    float2 v[KK];
    float m0 = -3.4e38f, m1 = -3.4e38f;
#pragma unroll
    for (int k = 0; k < KK; k++) {
        float2 t = __half22float2(*(const __half2*)(lp + k*DM));
        t.x *= 0.125f; t.y *= 0.125f;
        v[k] = t;
        m0 = fmaxf(m0, t.x); m1 = fmaxf(m1, t.y);
    }
    float s0 = 0.0f, s1 = 0.0f;
#pragma unroll
    for (int k = 0; k < KK; k++) {
        v[k].x = __expf(v[k].x - m0); s0 += v[k].x;
        v[k].y = __expf(v[k].y - m1); s1 += v[k].y;
    }
    float inv0 = 1.0f / s0, inv1 = 1.0f / s1;
    float a0 = 0.0f, a1 = 0.0f;
#pragma unroll
    for (int k = 0; k < KK; k++) {
        float p0 = v[k].x * inv0, p1 = v[k].y * inv1;
        float2 w = { p0, p1 };
        *(float2*)(ao + k*DM) = w;
        float2 fv = __half22float2(*(const __half2*)(vp + k*DM));
        a0 = fmaf(p0, fv.x, a0);
        a1 = fmaf(p1, fv.y, a1);
    }
    res_s[slot][d] = a0;
    res_s[slot][d+1] = a1;
    __syncthreads();

    float2 xv = *(const float2*)(g_x + (size_t)bn*DM + d);
    float o0 = b2[d] + xv.x;
    float o1 = b2[d+1] + xv.y;
#pragma unroll
    for (int e = 0; e < DM; e++) {
        float r = res_s[slot][e];
        o0 = fmaf(r, w2_s[e][d], o0);
        o1 = fmaf(r, w2_s[e][d+1], o1);
    }
    float2 ov = { o0, o1 };
    *(float2*)(out_res + (size_t)bn*DM + d) = ov;
}

extern "C" void kernel_launch(void* const* d_in, const int* in_sizes, int n_in,
                              void* d_out, int out_size) {
    const float* feat = (const float*)d_in[0];
    const float* xyz  = (const float*)d_in[1];
    const float* W1   = (const float*)d_in[2];
    const float* b1   = (const float*)d_in[3];
    const float* W2   = (const float*)d_in[4];
    const float* b2   = (const float*)d_in[5];
    const float* Wd1  = (const float*)d_in[6];
    const float* bd1  = (const float*)d_in[7];
    const float* Wd2  = (const float*)d_in[8];
    const float* bd2  = (const float*)d_in[9];
    const float* Wa   = (const float*)d_in[10];
    const float* ba   = (const float*)d_in[11];

    float* out_res  = (float*)d_out;
    float* out_attn = (float*)d_out + (size_t)BN * DM;

    cudaFuncSetAttribute(attn_gemm_mma, cudaFuncAttributeMaxDynamicSharedMemorySize, SMEM_GEMM);
    cudaFuncSetAttribute(knn_kernel, cudaFuncAttributeMaxDynamicSharedMemorySize, KNN_SMEM);

    prep_kernel<<<FC1_BLKS + WA_BLKS + WD_BLKS, 256>>>(feat, W1, b1, Wa, Wd1, Wd2);  // 0
    dim3 kg(NN/KQW, BB);
    knn_kernel<<<kg, 1024, KNN_SMEM>>>(xyz);                 // 1
    posenc_kernel<<<RR/POSB, 256>>>(xyz, bd1, bd2);          // 2
    dim3 gg(DK/TN, BN/TM);
    attn_gemm_mma<<<gg, 256, SMEM_GEMM>>>(ba);               // 3
    softmax_out<<<BN/8, 256>>>(W2, b2, out_res, out_attn);   // 4
}

// round 16
// speedup vs baseline: 1.0170x; 1.0170x over previous
#include <cuda_runtime.h>
#include <cuda_bf16.h>
#include <cuda_fp16.h>
#include <math.h>
#include <stdint.h>

#define BB 4
#define NN 8192
#define KK 24
#define DP 32
#define DM 64
#define PE 60
#define DK (DM*KK)        // 1536
#define BN (BB*NN)        // 32768
#define RR (BN*KK)        // 786432

// Scratch (allocation-free rule: __device__ globals)
__device__ float g_x[BN*DM];                  // fc1 output
__device__ int   g_knn[RR];                   // knn indices
__device__ __half g_pre[(size_t)RR*DM];       // fp16(q - kf + pos_enc)
__device__ __half g_vpe[(size_t)RR*DM];       // fp16(vf + pos_enc)
__device__ __half g_logit[(size_t)RR*DM];     // fp16 attn logits (pre-softmax)
__device__ __half g_wa[DK*DK];                // fp16 Wa
__device__ __half g_w1h[DM*DM];               // fp16 Wd1 [n=64][k=64], k 60..63 zero
__device__ __half g_w2h[DM*DM];               // fp16 Wd2 [n=64][k=64]

// ================= helpers (sm_80-compatible only) =================
__device__ __forceinline__ uint32_t smem_u32(const void* p) {
    uint32_t a;
    asm("{ .reg .u64 t; cvta.to.shared.u64 t, %1; cvt.u32.u64 %0, t; }" : "=r"(a) : "l"(p));
    return a;
}
#define SWZ(x) ((x) ^ (((x) >> 3) & 0x70))
__device__ __forceinline__ void cp16(uint32_t s, const void* g) {
    asm volatile("cp.async.cg.shared.global [%0], [%1], 16;" :: "r"(s), "l"(g));
}
__device__ __forceinline__ void ldsm4(uint32_t& r0, uint32_t& r1, uint32_t& r2, uint32_t& r3,
                                      uint32_t addr) {
    asm volatile("ldmatrix.sync.aligned.m8n8.x4.shared.b16 {%0,%1,%2,%3}, [%4];"
                 : "=r"(r0), "=r"(r1), "=r"(r2), "=r"(r3) : "r"(addr));
}
__device__ __forceinline__ void mma_fp16(float* c, const uint32_t* a, const uint32_t* b) {
    asm volatile("mma.sync.aligned.m16n8k16.row.col.f32.f16.f16.f32 "
                 "{%0,%1,%2,%3}, {%4,%5,%6,%7}, {%8,%9}, {%0,%1,%2,%3};"
                 : "+f"(c[0]), "+f"(c[1]), "+f"(c[2]), "+f"(c[3])
                 : "r"(a[0]), "r"(a[1]), "r"(a[2]), "r"(a[3]), "r"(b[0]), "r"(b[1]));
}
__device__ __forceinline__ uint32_t packh2(float a, float b) {
    __half2 h = __floats2half2_rn(a, b);
    return *(uint32_t*)&h;
}

// ================= prep: fc1 + Wa->fp16 + Wd transpose (one launch) =================
#define FC1_BLKS (BN*DM/256)         // 8192
#define WA_BLKS  (DK*DK/256)         // 9216
#define WD_BLKS  ((2*DM*DM+255)/256) // 32
__global__ void prep_kernel(const float* __restrict__ feat,
                            const float* __restrict__ W1,
                            const float* __restrict__ b1,
                            const float* __restrict__ Wa,
                            const float* __restrict__ Wd1,
                            const float* __restrict__ Wd2) {
    int bid = blockIdx.x;
    if (bid < FC1_BLKS) {
        int t = bid * 256 + threadIdx.x;
        int p = t >> 6, d = t & 63;
        const float* f = feat + (size_t)p * DP;
        const float* w = W1 + d * DP;
        float s = b1[d];
#pragma unroll
        for (int i = 0; i < DP; i++) s = fmaf(f[i], w[i], s);
        g_x[t] = s;
    } else if (bid < FC1_BLKS + WA_BLKS) {
        int t = (bid - FC1_BLKS) * 256 + threadIdx.x;
        g_wa[t] = __float2half(Wa[t]);
    } else {
        int t = (bid - FC1_BLKS - WA_BLKS) * 256 + threadIdx.x;
        if (t < DM*DM) {
            int n = t >> 6, k = t & 63;
            g_w1h[t] = __float2half(k < PE ? Wd1[n*PE + k] : 0.0f);
        } else if (t < 2*DM*DM) {
            int u = t - DM*DM;
            g_w2h[u] = __float2half(Wd2[u]);
        }
    }
}

// ================= KNN: warp-per-query, lane-distributed top-24 (R14 proven) =================
// 32-lane sorted list; lanes 0..23 = answer, 24..31 = overflow (stale-threshold safe).
#define KQW 16
#define KTILE 1024
#define FULLM 0xFFFFFFFFu
__global__ __launch_bounds__(512) void knn_kernel(const float* __restrict__ xyz) {
    __shared__ float4 s4[KTILE];
    const int tid = threadIdx.x;
    const int warp = tid >> 5, lane = tid & 31;
    const int b = blockIdx.y;
    const int q = blockIdx.x * KQW + warp;
    const float* base = xyz + (size_t)b * NN * 3;
    const float qx = base[3*q], qy = base[3*q+1], qz = base[3*q+2];
    const float qs = qx*qx + qy*qy + qz*qz;

    float kd = 3.4e38f;          // per-lane list entry
    int   ki = 0x7fffffff;
    float wd = 3.4e38f;          // cached lane-23 worst (stale = conservative)

    for (int j0 = 0; j0 < NN; j0 += KTILE) {
        for (int t = tid; t < KTILE; t += 512) {
            float x = base[3*(j0+t)], y = base[3*(j0+t)+1], z = base[3*(j0+t)+2];
            s4[t] = make_float4(x, y, z, x*x + y*y + z*z);
        }
        __syncthreads();
        for (int jj = 0; jj < KTILE; jj += 64) {
            float4 c1 = s4[jj + lane];
            float4 c2 = s4[jj + 32 + lane];
            float d1 = (qs + c1.w) - 2.0f * (qx*c1.x + qy*c1.y + qz*c1.z);
            float d2 = (qs + c2.w) - 2.0f * (qx*c2.x + qy*c2.y + qz*c2.z);
            int i1 = j0 + jj + lane;
            int i2 = i1 + 32;
            unsigned m1 = __ballot_sync(FULLM, d1 <= wd);
            unsigned m2 = __ballot_sync(FULLM, d2 <= wd);
            if ((m1 | m2) == 0) continue;
#pragma unroll
            for (int half = 0; half < 2; half++) {
                unsigned m = half ? m2 : m1;
                float dcur = half ? d2 : d1;
                int icur = half ? i2 : i1;
                while (m) {
                    int src = __ffs(m) - 1; m &= m - 1;
                    float cd = __shfl_sync(FULLM, dcur, src);
                    int   ci = __shfl_sync(FULLM, icur, src);
                    float ud = __shfl_up_sync(FULLM, kd, 1);
                    int   ui = __shfl_up_sync(FULLM, ki, 1);
                    bool self_gt = (kd > cd) || (kd == cd && ki > ci);
                    bool prev_gt = (lane != 0) && ((ud > cd) || (ud == cd && ui > ci));
                    if (self_gt) {
                        kd = prev_gt ? ud : cd;
                        ki = prev_gt ? ui : ci;
                    }
                }
            }
            wd = __shfl_sync(FULLM, kd, 23);   // refresh worst once per group
        }
        __syncthreads();
    }
    if (lane < KK) g_knn[((size_t)b * NN + q) * KK + lane] = ki;
}

// ================= posenc: b2b tensor-core MMA (R14 proven: 64 rows, 128 thr) =================
#define POSB 64
__global__ __launch_bounds__(128) void posenc_kernel(const float* __restrict__ xyz,
                                                     const float* __restrict__ bd1,
                                                     const float* __restrict__ bd2) {
    __shared__ __align__(16) char w1s[8192];
    __shared__ __align__(16) char w2s[8192];
    __shared__ __align__(16) char pes[8192];
    __shared__ float dxs[POSB*3];
    __shared__ float om[16];
    __shared__ float b1s[DM], b2s[DM];
    __shared__ int knn_s[POSB];

    const int tid = threadIdx.x;
    const int lane = tid & 31, warp = tid >> 5;
    const int rbase = blockIdx.x * POSB;
    const uint32_t w1a = smem_u32(w1s), w2a = smem_u32(w2s), pea = smem_u32(pes);

    for (int gi = tid; gi < 512; gi += 128) {
        int row = gi >> 3, seg = gi & 7;
        uint32_t so = SWZ((uint32_t)(row*128 + seg*16));
        cp16(w1a + so, g_w1h + row*64 + seg*8);
        cp16(w2a + so, g_w2h + row*64 + seg*8);
    }
    asm volatile("cp.async.commit_group;" ::: "memory");
    if (tid < 10) om[tid] = exp2f(-(float)tid * 1.3287712379549449f);  // 10000^(-tid/10)
    if (tid < DM) { b1s[tid] = bd1[tid]; b2s[tid] = bd2[tid]; }
    if (tid < POSB) {
        int row = rbase + tid;
        int bn = row / KK;
        int b = bn / NN, n = bn % NN;
        int idx = g_knn[row];
        knn_s[tid] = idx;
        const float* xb = xyz + (size_t)b * NN * 3;
        dxs[tid*3+0] = xb[3*n+0] - xb[3*idx+0];
        dxs[tid*3+1] = xb[3*n+1] - xb[3*idx+1];
        dxs[tid*3+2] = xb[3*n+2] - xb[3*idx+2];
    }
    asm volatile("cp.async.wait_group 0;" ::: "memory");
    __syncthreads();

    for (int p = tid; p < POSB*30; p += 128) {
        int r = p / 30, j2 = p % 30;
        float v[2];
#pragma unroll
        for (int u = 0; u < 2; u++) {
            int j = j2*2 + u;
            int axis = j / 20, tt = j % 20;
            int oi = (tt < 10) ? tt : tt - 10;
            float ang = dxs[r*3 + axis] * om[oi];
            v[u] = (tt < 10) ? __sinf(ang) : __cosf(ang);
        }
        *(uint32_t*)(pes + SWZ((uint32_t)(r*128 + j2*4))) = packh2(v[0], v[1]);
    }
    for (int r = tid; r < POSB; r += 128) {
        *(uint32_t*)(pes + SWZ((uint32_t)(r*128 + 120))) = 0;
        *(uint32_t*)(pes + SWZ((uint32_t)(r*128 + 124))) = 0;
    }
    __syncthreads();

    const int g = lane >> 2, tg = lane & 3;
    const int arow = lane & 15;
    const int akx  = (lane >> 4) << 4;
    const int brow = (lane & 7) + ((lane >> 4) << 3);
    const int bkx  = ((lane >> 3) & 1) << 4;
    const int wbase = warp * 16;

    float acc1[8][4];
#pragma unroll
    for (int j = 0; j < 8; j++)
#pragma unroll
        for (int i = 0; i < 4; i++) acc1[j][i] = 0.0f;
#pragma unroll
    for (int kt = 0; kt < 4; kt++) {
        int kb = kt * 32;
        uint32_t af[4];
        {
            int row = wbase + arow;
            uint32_t off = (uint32_t)row*128 + (uint32_t)((kb + akx) ^ ((row & 7) << 4));
            ldsm4(af[0], af[1], af[2], af[3], pea + off);
        }
        uint32_t bf[8][2];
#pragma unroll
        for (int nj = 0; nj < 4; nj++) {
            int row = nj*16 + brow;
            uint32_t off = (uint32_t)row*128 + (uint32_t)((kb + bkx) ^ ((row & 7) << 4));
            ldsm4(bf[nj*2][0], bf[nj*2][1], bf[nj*2+1][0], bf[nj*2+1][1], w1a + off);
        }
#pragma unroll
        for (int j = 0; j < 8; j++) mma_fp16(acc1[j], af, bf[j]);
    }

    uint32_t a2[4][4];
#pragma unroll
    for (int j = 0; j < 8; j++) {
        int c0 = 8*j + 2*tg;
        float h0 = fmaxf(acc1[j][0] + b1s[c0],   0.0f);
        float h1 = fmaxf(acc1[j][1] + b1s[c0+1], 0.0f);
        float h2 = fmaxf(acc1[j][2] + b1s[c0],   0.0f);
        float h3 = fmaxf(acc1[j][3] + b1s[c0+1], 0.0f);
        a2[j>>1][(j&1)*2 + 0] = packh2(h0, h1);
        a2[j>>1][(j&1)*2 + 1] = packh2(h2, h3);
    }

    float acc2[8][4];
#pragma unroll
    for (int j = 0; j < 8; j++)
#pragma unroll
        for (int i = 0; i < 4; i++) acc2[j][i] = 0.0f;
#pragma unroll
    for (int kt = 0; kt < 4; kt++) {
        int kb = kt * 32;
        uint32_t bf[8][2];
#pragma unroll
        for (int nj = 0; nj < 4; nj++) {
            int row = nj*16 + brow;
            uint32_t off = (uint32_t)row*128 + (uint32_t)((kb + bkx) ^ ((row & 7) << 4));
            ldsm4(bf[nj*2][0], bf[nj*2][1], bf[nj*2+1][0], bf[nj*2+1][1], w2a + off);
        }
#pragma unroll
        for (int j = 0; j < 8; j++) mma_fp16(acc2[j], a2[kt], bf[j]);
    }

#pragma unroll
    for (int rr = 0; rr < 2; rr++) {
        int lrow = wbase + g + rr*8;
        int row = rbase + lrow;
        int bn = row / KK;
        int b = bn / NN;
        int idx = knn_s[lrow];
        const float* qp = g_x + (size_t)bn * DM;
        const float* kp = g_x + ((size_t)b * NN + idx) * DM;
        __half* ph = g_pre + (size_t)row * DM;
        __half* vp = g_vpe + (size_t)row * DM;
#pragma unroll
        for (int j = 0; j < 8; j++) {
            int c0 = 8*j + 2*tg;
            float pos0 = acc2[j][rr*2+0] + b2s[c0];
            float pos1 = acc2[j][rr*2+1] + b2s[c0+1];
            float2 qv = *(const float2*)(qp + c0);
            float2 kf = *(const float2*)(kp + c0);
            *(uint32_t*)(ph + c0) = packh2(qv.x - kf.x + pos0, qv.y - kf.y + pos1);
            *(uint32_t*)(vp + c0) = packh2(kf.x + pos0, kf.y + pos1);
        }
    }
}

// ================= attention GEMM (R11/R14 geometry, fp16 logit epilogue) =================
#define TM 128
#define TN 128
#define KC 64
#define NCH (DK/KC)          // 24
#define NSTG 3
#define STG_B 32768          // A 16K | B 16K
#define SMEM_GEMM (NSTG*STG_B)  // 98304

__global__ void __launch_bounds__(256, 2)
attn_gemm_mma(const float* __restrict__ ba) {
    extern __shared__ char smem[];
    const uint32_t sb = smem_u32(smem);
    const int tid = threadIdx.x;
    const int warp = tid >> 5, lane = tid & 31;
    const int bm = blockIdx.y * TM;
    const int bn = blockIdx.x * TN;
    const int wm = (warp >> 2) * 64;     // 0/64
    const int wn = (warp & 3) * 32;      // 0/32/64/96

    const __half* Ap = g_pre + (size_t)bm * DK;
    const __half* Bp = g_wa  + (size_t)bn * DK;

    auto load_chunk = [&](int c, int s) {
        int kt = c * KC;
        uint32_t st = sb + s * STG_B;
#pragma unroll
        for (int i = 0; i < 4; i++) {
            int u = tid + i * 256;
            int row = u >> 3, seg = u & 7;          // 128 rows x 8 x 16B
            uint32_t so = SWZ((uint32_t)(row * 128 + seg * 16));
            size_t go = (size_t)row * DK + kt + seg * 8;
            cp16(st + so,          Ap + go);
            cp16(st + 16384 + so,  Bp + go);
        }
        asm volatile("cp.async.commit_group;" ::: "memory");
    };

    const int arow = lane & 15;
    const int akx  = (lane >> 4) << 4;
    const int brow = (lane & 7) + ((lane >> 4) << 3);
    const int bkx  = ((lane >> 3) & 1) << 4;

    float acc[4][4][4];
#pragma unroll
    for (int a = 0; a < 4; a++)
#pragma unroll
        for (int b = 0; b < 4; b++)
#pragma unroll
            for (int c = 0; c < 4; c++) acc[a][b][c] = 0.0f;

    load_chunk(0, 0);
    load_chunk(1, 1);

    for (int c = 0; c < NCH; c++) {
        int s = c % NSTG;
        asm volatile("cp.async.wait_group 1;" ::: "memory");
        __syncthreads();
        if (c + 2 < NCH) load_chunk(c + 2, (c + 2) % NSTG);

        uint32_t st = sb + s * STG_B;
#pragma unroll
        for (int k16 = 0; k16 < 4; k16++) {
            int kb = k16 * 32;
            uint32_t af[4][4];
#pragma unroll
            for (int mi = 0; mi < 4; mi++) {
                int row = wm + mi * 16 + arow;
                uint32_t off = (uint32_t)row * 128 + (uint32_t)((kb + akx) ^ ((row & 7) << 4));
                ldsm4(af[mi][0], af[mi][1], af[mi][2], af[mi][3], st + off);
            }
            uint32_t bf[4][2];
#pragma unroll
            for (int nj = 0; nj < 2; nj++) {
                int row = wn + nj * 16 + brow;
                uint32_t off = (uint32_t)row * 128 + (uint32_t)((kb + bkx) ^ ((row & 7) << 4));
                ldsm4(bf[nj*2][0], bf[nj*2][1], bf[nj*2+1][0], bf[nj*2+1][1], st + 16384 + off);
            }
#pragma unroll
            for (int mi = 0; mi < 4; mi++)
#pragma unroll
                for (int ni = 0; ni < 4; ni++)
                    mma_fp16(acc[mi][ni], af[mi], bf[ni]);
        }
    }

    // epilogue: bias + fp16 logit store
    const int g = lane >> 2, tg = lane & 3;
#pragma unroll
    for (int mi = 0; mi < 4; mi++) {
        int r0 = bm + wm + mi * 16 + g;
        __half* o0 = g_logit + (size_t)r0 * DK;
        __half* o1 = g_logit + (size_t)(r0 + 8) * DK;
#pragma unroll
        for (int ni = 0; ni < 4; ni++) {
            int col = bn + wn + ni * 8 + tg * 2;
            float bv0 = __ldg(&ba[col]), bv1 = __ldg(&ba[col + 1]);
            *(uint32_t*)(o0 + col) = packh2(acc[mi][ni][0] + bv0, acc[mi][ni][1] + bv1);
            *(uint32_t*)(o1 + col) = packh2(acc[mi][ni][2] + bv0, acc[mi][ni][3] + bv1);
        }
    }
}

// ================= softmax + weighted sum + fc2 + residual (fp16 logits in) =================
__global__ __launch_bounds__(256) void softmax_out(const float* __restrict__ W2,
                                                   const float* __restrict__ b2,
                                                   float* __restrict__ out_res,
                                                   float* __restrict__ out_attn) {
    __shared__ float w2_s[DM][DM];     // transposed: w2_s[e][d]
    __shared__ float res_s[8][DM];
    int tid = threadIdx.x;
    int slot = tid >> 5, d2 = tid & 31;
    int d = d2 * 2;
    for (int t = tid; t < DM*DM; t += 256) { int dd = t / DM, e = t % DM; w2_s[e][dd] = W2[t]; }
    __syncthreads();

    int bn = blockIdx.x * 8 + slot;
    const __half* lp = g_logit + (size_t)bn * KK * DM + d;
    const __half* vp = g_vpe + (size_t)bn * KK * DM + d;
    float* ao = out_attn + (size_t)bn * KK * DM + d;

    float2 v[KK];
    float m0 = -3.4e38f, m1 = -3.4e38f;
#pragma unroll
    for (int k = 0; k < KK; k++) {
        float2 t = __half22float2(*(const __half2*)(lp + k*DM));
        t.x *= 0.125f; t.y *= 0.125f;
        v[k] = t;
        m0 = fmaxf(m0, t.x); m1 = fmaxf(m1, t.y);
    }
    float s0 = 0.0f, s1 = 0.0f;
#pragma unroll
    for (int k = 0; k < KK; k++) {
        v[k].x = __expf(v[k].x - m0); s0 += v[k].x;
        v[k].y = __expf(v[k].y - m1); s1 += v[k].y;
    }
    float inv0 = 1.0f / s0, inv1 = 1.0f / s1;
    float a0 = 0.0f, a1 = 0.0f;
#pragma unroll
    for (int k = 0; k < KK; k++) {
        float p0 = v[k].x * inv0, p1 = v[k].y * inv1;
        float2 w = { p0, p1 };
        *(float2*)(ao + k*DM) = w;
        float2 fv = __half22float2(*(const __half2*)(vp + k*DM));
        a0 = fmaf(p0, fv.x, a0);
        a1 = fmaf(p1, fv.y, a1);
    }
    res_s[slot][d] = a0;
    res_s[slot][d+1] = a1;
    __syncthreads();

    float2 xv = *(const float2*)(g_x + (size_t)bn*DM + d);
    float o0 = b2[d] + xv.x;
    float o1 = b2[d+1] + xv.y;
#pragma unroll
    for (int e = 0; e < DM; e++) {
        float r = res_s[slot][e];
        o0 = fmaf(r, w2_s[e][d], o0);
        o1 = fmaf(r, w2_s[e][d+1], o1);
    }
    float2 ov = { o0, o1 };
    *(float2*)(out_res + (size_t)bn*DM + d) = ov;
}

extern "C" void kernel_launch(void* const* d_in, const int* in_sizes, int n_in,
                              void* d_out, int out_size) {
    const float* feat = (const float*)d_in[0];
    const float* xyz  = (const float*)d_in[1];
    const float* W1   = (const float*)d_in[2];
    const float* b1   = (const float*)d_in[3];
    const float* W2   = (const float*)d_in[4];
    const float* b2   = (const float*)d_in[5];
    const float* Wd1  = (const float*)d_in[6];
    const float* bd1  = (const float*)d_in[7];
    const float* Wd2  = (const float*)d_in[8];
    const float* bd2  = (const float*)d_in[9];
    const float* Wa   = (const float*)d_in[10];
    const float* ba   = (const float*)d_in[11];

    float* out_res  = (float*)d_out;
    float* out_attn = (float*)d_out + (size_t)BN * DM;

    cudaFuncSetAttribute(attn_gemm_mma, cudaFuncAttributeMaxDynamicSharedMemorySize, SMEM_GEMM);

    prep_kernel<<<FC1_BLKS + WA_BLKS + WD_BLKS, 256>>>(feat, W1, b1, Wa, Wd1, Wd2);  // 0
    dim3 kg(NN/KQW, BB);
    knn_kernel<<<kg, 512>>>(xyz);                            // 1
    posenc_kernel<<<RR/POSB, 128>>>(xyz, bd1, bd2);          // 2
    dim3 gg(DK/TN, BN/TM);
    attn_gemm_mma<<<gg, 256, SMEM_GEMM>>>(ba);               // 3
    softmax_out<<<BN/8, 256>>>(W2, b2, out_res, out_attn);   // 4
}

// round 17
// speedup vs baseline: 1.0444x; 1.0269x over previous
#include <cuda_runtime.h>
#include <cuda_bf16.h>
#include <cuda_fp16.h>
#include <math.h>
#include <stdint.h>

#define BB 4
#define NN 8192
#define KK 24
#define DP 32
#define DM 64
#define PE 60
#define DK (DM*KK)        // 1536
#define BN (BB*NN)        // 32768
#define RR (BN*KK)        // 786432

// Scratch (allocation-free rule: __device__ globals)
__device__ float g_x[BN*DM];                  // fc1 output
__device__ int   g_knn[RR];                   // knn indices
__device__ __half g_pre[(size_t)RR*DM];       // fp16(q - kf + pos_enc)
__device__ __half g_vpe[(size_t)RR*DM];       // fp16(vf + pos_enc)
__device__ __half g_logit[(size_t)RR*DM];     // fp16 attn logits (pre-scaled by 1/8)
__device__ __half g_wa[DK*DK];                // fp16 Wa/8
__device__ float g_ba[DK];                    // ba/8
__device__ __half g_w1h[DM*DM];               // fp16 Wd1 [n=64][k=64], k 60..63 zero
__device__ __half g_w2h[DM*DM];               // fp16 Wd2 [n=64][k=64]

// ================= helpers (sm_80-compatible only) =================
__device__ __forceinline__ uint32_t smem_u32(const void* p) {
    uint32_t a;
    asm("{ .reg .u64 t; cvta.to.shared.u64 t, %1; cvt.u32.u64 %0, t; }" : "=r"(a) : "l"(p));
    return a;
}
#define SWZ(x) ((x) ^ (((x) >> 3) & 0x70))
__device__ __forceinline__ void cp16(uint32_t s, const void* g) {
    asm volatile("cp.async.cg.shared.global [%0], [%1], 16;" :: "r"(s), "l"(g));
}
__device__ __forceinline__ void ldsm4(uint32_t& r0, uint32_t& r1, uint32_t& r2, uint32_t& r3,
                                      uint32_t addr) {
    asm volatile("ldmatrix.sync.aligned.m8n8.x4.shared.b16 {%0,%1,%2,%3}, [%4];"
                 : "=r"(r0), "=r"(r1), "=r"(r2), "=r"(r3) : "r"(addr));
}
__device__ __forceinline__ void mma_fp16(float* c, const uint32_t* a, const uint32_t* b) {
    asm volatile("mma.sync.aligned.m16n8k16.row.col.f32.f16.f16.f32 "
                 "{%0,%1,%2,%3}, {%4,%5,%6,%7}, {%8,%9}, {%0,%1,%2,%3};"
                 : "+f"(c[0]), "+f"(c[1]), "+f"(c[2]), "+f"(c[3])
                 : "r"(a[0]), "r"(a[1]), "r"(a[2]), "r"(a[3]), "r"(b[0]), "r"(b[1]));
}
__device__ __forceinline__ uint32_t packh2(float a, float b) {
    __half2 h = __floats2half2_rn(a, b);
    return *(uint32_t*)&h;
}

// ================= prep: fc1 + Wa/8->fp16 + ba/8 + Wd transpose (one launch) =================
#define FC1_BLKS (BN*DM/256)         // 8192
#define WA_BLKS  (DK*DK/256)         // 9216
#define WD_BLKS  ((2*DM*DM+255)/256) // 32
#define BA_BLKS  (DK/256)            // 6
__global__ void prep_kernel(const float* __restrict__ feat,
                            const float* __restrict__ W1,
                            const float* __restrict__ b1,
                            const float* __restrict__ Wa,
                            const float* __restrict__ ba,
                            const float* __restrict__ Wd1,
                            const float* __restrict__ Wd2) {
    int bid = blockIdx.x;
    if (bid < FC1_BLKS) {
        int t = bid * 256 + threadIdx.x;
        int p = t >> 6, d = t & 63;
        const float* f = feat + (size_t)p * DP;
        const float* w = W1 + d * DP;
        float s = b1[d];
#pragma unroll
        for (int i = 0; i < DP; i++) s = fmaf(f[i], w[i], s);
        g_x[t] = s;
    } else if (bid < FC1_BLKS + WA_BLKS) {
        int t = (bid - FC1_BLKS) * 256 + threadIdx.x;
        g_wa[t] = __float2half(Wa[t] * 0.125f);   // exact (power of 2)
    } else if (bid < FC1_BLKS + WA_BLKS + WD_BLKS) {
        int t = (bid - FC1_BLKS - WA_BLKS) * 256 + threadIdx.x;
        if (t < DM*DM) {
            int n = t >> 6, k = t & 63;
            g_w1h[t] = __float2half(k < PE ? Wd1[n*PE + k] : 0.0f);
        } else if (t < 2*DM*DM) {
            int u = t - DM*DM;
            g_w2h[u] = __float2half(Wd2[u]);
        }
    } else {
        int t = (bid - FC1_BLKS - WA_BLKS - WD_BLKS) * 256 + threadIdx.x;
        g_ba[t] = ba[t] * 0.125f;
    }
}

// ================= KNN: warp-per-query, lane-distributed top-24 (R14 proven) =================
#define KQW 16
#define KTILE 1024
#define FULLM 0xFFFFFFFFu
__global__ __launch_bounds__(512) void knn_kernel(const float* __restrict__ xyz) {
    __shared__ float4 s4[KTILE];
    const int tid = threadIdx.x;
    const int warp = tid >> 5, lane = tid & 31;
    const int b = blockIdx.y;
    const int q = blockIdx.x * KQW + warp;
    const float* base = xyz + (size_t)b * NN * 3;
    const float qx = base[3*q], qy = base[3*q+1], qz = base[3*q+2];
    const float qs = qx*qx + qy*qy + qz*qz;

    float kd = 3.4e38f;          // per-lane list entry (lanes 0..23 = answer)
    int   ki = 0x7fffffff;
    float wd = 3.4e38f;          // cached lane-23 worst (stale = conservative)

    for (int j0 = 0; j0 < NN; j0 += KTILE) {
        for (int t = tid; t < KTILE; t += 512) {
            float x = base[3*(j0+t)], y = base[3*(j0+t)+1], z = base[3*(j0+t)+2];
            s4[t] = make_float4(x, y, z, x*x + y*y + z*z);
        }
        __syncthreads();
        for (int jj = 0; jj < KTILE; jj += 64) {
            float4 c1 = s4[jj + lane];
            float4 c2 = s4[jj + 32 + lane];
            float d1 = (qs + c1.w) - 2.0f * (qx*c1.x + qy*c1.y + qz*c1.z);
            float d2 = (qs + c2.w) - 2.0f * (qx*c2.x + qy*c2.y + qz*c2.z);
            int i1 = j0 + jj + lane;
            int i2 = i1 + 32;
            unsigned m1 = __ballot_sync(FULLM, d1 <= wd);
            unsigned m2 = __ballot_sync(FULLM, d2 <= wd);
            if ((m1 | m2) == 0) continue;
#pragma unroll
            for (int half = 0; half < 2; half++) {
                unsigned m = half ? m2 : m1;
                float dcur = half ? d2 : d1;
                int icur = half ? i2 : i1;
                while (m) {
                    int src = __ffs(m) - 1; m &= m - 1;
                    float cd = __shfl_sync(FULLM, dcur, src);
                    int   ci = __shfl_sync(FULLM, icur, src);
                    float ud = __shfl_up_sync(FULLM, kd, 1);
                    int   ui = __shfl_up_sync(FULLM, ki, 1);
                    bool self_gt = (kd > cd) || (kd == cd && ki > ci);
                    bool prev_gt = (lane != 0) && ((ud > cd) || (ud == cd && ui > ci));
                    if (self_gt) {
                        kd = prev_gt ? ud : cd;
                        ki = prev_gt ? ui : ci;
                    }
                }
            }
            wd = __shfl_sync(FULLM, kd, 23);   // refresh worst once per group
        }
        __syncthreads();
    }
    if (lane < KK) g_knn[((size_t)b * NN + q) * KK + lane] = ki;
}

// ================= posenc: b2b tensor-core MMA (R14 proven: 64 rows, 128 thr) =================
#define POSB 64
__global__ __launch_bounds__(128) void posenc_kernel(const float* __restrict__ xyz,
                                                     const float* __restrict__ bd1,
                                                     const float* __restrict__ bd2) {
    __shared__ __align__(16) char w1s[8192];
    __shared__ __align__(16) char w2s[8192];
    __shared__ __align__(16) char pes[8192];
    __shared__ float dxs[POSB*3];
    __shared__ float om[16];
    __shared__ float b1s[DM], b2s[DM];
    __shared__ int knn_s[POSB];

    const int tid = threadIdx.x;
    const int lane = tid & 31, warp = tid >> 5;
    const int rbase = blockIdx.x * POSB;
    const uint32_t w1a = smem_u32(w1s), w2a = smem_u32(w2s), pea = smem_u32(pes);

    for (int gi = tid; gi < 512; gi += 128) {
        int row = gi >> 3, seg = gi & 7;
        uint32_t so = SWZ((uint32_t)(row*128 + seg*16));
        cp16(w1a + so, g_w1h + row*64 + seg*8);
        cp16(w2a + so, g_w2h + row*64 + seg*8);
    }
    asm volatile("cp.async.commit_group;" ::: "memory");
    if (tid < 10) om[tid] = exp2f(-(float)tid * 1.3287712379549449f);  // 10000^(-tid/10)
    if (tid < DM) { b1s[tid] = bd1[tid]; b2s[tid] = bd2[tid]; }
    if (tid < POSB) {
        int row = rbase + tid;
        int bn = row / KK;
        int b = bn / NN, n = bn % NN;
        int idx = g_knn[row];
        knn_s[tid] = idx;
        const float* xb = xyz + (size_t)b * NN * 3;
        dxs[tid*3+0] = xb[3*n+0] - xb[3*idx+0];
        dxs[tid*3+1] = xb[3*n+1] - xb[3*idx+1];
        dxs[tid*3+2] = xb[3*n+2] - xb[3*idx+2];
    }
    asm volatile("cp.async.wait_group 0;" ::: "memory");
    __syncthreads();

    for (int p = tid; p < POSB*30; p += 128) {
        int r = p / 30, j2 = p % 30;
        float v[2];
#pragma unroll
        for (int u = 0; u < 2; u++) {
            int j = j2*2 + u;
            int axis = j / 20, tt = j % 20;
            int oi = (tt < 10) ? tt : tt - 10;
            float ang = dxs[r*3 + axis] * om[oi];
            v[u] = (tt < 10) ? __sinf(ang) : __cosf(ang);
        }
        *(uint32_t*)(pes + SWZ((uint32_t)(r*128 + j2*4))) = packh2(v[0], v[1]);
    }
    for (int r = tid; r < POSB; r += 128) {
        *(uint32_t*)(pes + SWZ((uint32_t)(r*128 + 120))) = 0;
        *(uint32_t*)(pes + SWZ((uint32_t)(r*128 + 124))) = 0;
    }
    __syncthreads();

    const int g = lane >> 2, tg = lane & 3;
    const int arow = lane & 15;
    const int akx  = (lane >> 4) << 4;
    const int brow = (lane & 7) + ((lane >> 4) << 3);
    const int bkx  = ((lane >> 3) & 1) << 4;
    const int wbase = warp * 16;

    float acc1[8][4];
#pragma unroll
    for (int j = 0; j < 8; j++)
#pragma unroll
        for (int i = 0; i < 4; i++) acc1[j][i] = 0.0f;
#pragma unroll
    for (int kt = 0; kt < 4; kt++) {
        int kb = kt * 32;
        uint32_t af[4];
        {
            int row = wbase + arow;
            uint32_t off = (uint32_t)row*128 + (uint32_t)((kb + akx) ^ ((row & 7) << 4));
            ldsm4(af[0], af[1], af[2], af[3], pea + off);
        }
        uint32_t bf[8][2];
#pragma unroll
        for (int nj = 0; nj < 4; nj++) {
            int row = nj*16 + brow;
            uint32_t off = (uint32_t)row*128 + (uint32_t)((kb + bkx) ^ ((row & 7) << 4));
            ldsm4(bf[nj*2][0], bf[nj*2][1], bf[nj*2+1][0], bf[nj*2+1][1], w1a + off);
        }
#pragma unroll
        for (int j = 0; j < 8; j++) mma_fp16(acc1[j], af, bf[j]);
    }

    uint32_t a2[4][4];
#pragma unroll
    for (int j = 0; j < 8; j++) {
        int c0 = 8*j + 2*tg;
        float h0 = fmaxf(acc1[j][0] + b1s[c0],   0.0f);
        float h1 = fmaxf(acc1[j][1] + b1s[c0+1], 0.0f);
        float h2 = fmaxf(acc1[j][2] + b1s[c0],   0.0f);
        float h3 = fmaxf(acc1[j][3] + b1s[c0+1], 0.0f);
        a2[j>>1][(j&1)*2 + 0] = packh2(h0, h1);
        a2[j>>1][(j&1)*2 + 1] = packh2(h2, h3);
    }

    float acc2[8][4];
#pragma unroll
    for (int j = 0; j < 8; j++)
#pragma unroll
        for (int i = 0; i < 4; i++) acc2[j][i] = 0.0f;
#pragma unroll
    for (int kt = 0; kt < 4; kt++) {
        int kb = kt * 32;
        uint32_t bf[8][2];
#pragma unroll
        for (int nj = 0; nj < 4; nj++) {
            int row = nj*16 + brow;
            uint32_t off = (uint32_t)row*128 + (uint32_t)((kb + bkx) ^ ((row & 7) << 4));
            ldsm4(bf[nj*2][0], bf[nj*2][1], bf[nj*2+1][0], bf[nj*2+1][1], w2a + off);
        }
#pragma unroll
        for (int j = 0; j < 8; j++) mma_fp16(acc2[j], a2[kt], bf[j]);
    }

#pragma unroll
    for (int rr = 0; rr < 2; rr++) {
        int lrow = wbase + g + rr*8;
        int row = rbase + lrow;
        int bn = row / KK;
        int b = bn / NN;
        int idx = knn_s[lrow];
        const float* qp = g_x + (size_t)bn * DM;
        const float* kp = g_x + ((size_t)b * NN + idx) * DM;
        __half* ph = g_pre + (size_t)row * DM;
        __half* vp = g_vpe + (size_t)row * DM;
#pragma unroll
        for (int j = 0; j < 8; j++) {
            int c0 = 8*j + 2*tg;
            float pos0 = acc2[j][rr*2+0] + b2s[c0];
            float pos1 = acc2[j][rr*2+1] + b2s[c0+1];
            float2 qv = *(const float2*)(qp + c0);
            float2 kf = *(const float2*)(kp + c0);
            *(uint32_t*)(ph + c0) = packh2(qv.x - kf.x + pos0, qv.y - kf.y + pos1);
            *(uint32_t*)(vp + c0) = packh2(kf.x + pos0, kf.y + pos1);
        }
    }
}

// ================= attention GEMM (frozen geometry, fp16 logit epilogue) =================
#define TM 128
#define TN 128
#define KC 64
#define NCH (DK/KC)          // 24
#define NSTG 3
#define STG_B 32768          // A 16K | B 16K
#define SMEM_GEMM (NSTG*STG_B)  // 98304

__global__ void __launch_bounds__(256, 2)
attn_gemm_mma() {
    extern __shared__ char smem[];
    const uint32_t sb = smem_u32(smem);
    const int tid = threadIdx.x;
    const int warp = tid >> 5, lane = tid & 31;
    const int bm = blockIdx.y * TM;
    const int bn = blockIdx.x * TN;
    const int wm = (warp >> 2) * 64;     // 0/64
    const int wn = (warp & 3) * 32;      // 0/32/64/96

    const __half* Ap = g_pre + (size_t)bm * DK;
    const __half* Bp = g_wa  + (size_t)bn * DK;

    auto load_chunk = [&](int c, int s) {
        int kt = c * KC;
        uint32_t st = sb + s * STG_B;
#pragma unroll
        for (int i = 0; i < 4; i++) {
            int u = tid + i * 256;
            int row = u >> 3, seg = u & 7;          // 128 rows x 8 x 16B
            uint32_t so = SWZ((uint32_t)(row * 128 + seg * 16));
            size_t go = (size_t)row * DK + kt + seg * 8;
            cp16(st + so,          Ap + go);
            cp16(st + 16384 + so,  Bp + go);
        }
        asm volatile("cp.async.commit_group;" ::: "memory");
    };

    const int arow = lane & 15;
    const int akx  = (lane >> 4) << 4;
    const int brow = (lane & 7) + ((lane >> 4) << 3);
    const int bkx  = ((lane >> 3) & 1) << 4;

    float acc[4][4][4];
#pragma unroll
    for (int a = 0; a < 4; a++)
#pragma unroll
        for (int b = 0; b < 4; b++)
#pragma unroll
            for (int c = 0; c < 4; c++) acc[a][b][c] = 0.0f;

    load_chunk(0, 0);
    load_chunk(1, 1);

    for (int c = 0; c < NCH; c++) {
        int s = c % NSTG;
        asm volatile("cp.async.wait_group 1;" ::: "memory");
        __syncthreads();
        if (c + 2 < NCH) load_chunk(c + 2, (c + 2) % NSTG);

        uint32_t st = sb + s * STG_B;
#pragma unroll
        for (int k16 = 0; k16 < 4; k16++) {
            int kb = k16 * 32;
            uint32_t af[4][4];
#pragma unroll
            for (int mi = 0; mi < 4; mi++) {
                int row = wm + mi * 16 + arow;
                uint32_t off = (uint32_t)row * 128 + (uint32_t)((kb + akx) ^ ((row & 7) << 4));
                ldsm4(af[mi][0], af[mi][1], af[mi][2], af[mi][3], st + off);
            }
            uint32_t bf[4][2];
#pragma unroll
            for (int nj = 0; nj < 2; nj++) {
                int row = wn + nj * 16 + brow;
                uint32_t off = (uint32_t)row * 128 + (uint32_t)((kb + bkx) ^ ((row & 7) << 4));
                ldsm4(bf[nj*2][0], bf[nj*2][1], bf[nj*2+1][0], bf[nj*2+1][1], st + 16384 + off);
            }
#pragma unroll
            for (int mi = 0; mi < 4; mi++)
#pragma unroll
                for (int ni = 0; ni < 4; ni++)
                    mma_fp16(acc[mi][ni], af[mi], bf[ni]);
        }
    }

    // epilogue: bias (pre-scaled) + fp16 logit store
    const int g = lane >> 2, tg = lane & 3;
#pragma unroll
    for (int mi = 0; mi < 4; mi++) {
        int r0 = bm + wm + mi * 16 + g;
        __half* o0 = g_logit + (size_t)r0 * DK;
        __half* o1 = g_logit + (size_t)(r0 + 8) * DK;
#pragma unroll
        for (int ni = 0; ni < 4; ni++) {
            int col = bn + wn + ni * 8 + tg * 2;
            float bv0 = g_ba[col], bv1 = g_ba[col + 1];
            *(uint32_t*)(o0 + col) = packh2(acc[mi][ni][0] + bv0, acc[mi][ni][1] + bv1);
            *(uint32_t*)(o1 + col) = packh2(acc[mi][ni][2] + bv0, acc[mi][ni][3] + bv1);
        }
    }
}

// ================= softmax + weighted sum + fc2 + residual (pre-scaled fp16 logits) =================
__global__ __launch_bounds__(256) void softmax_out(const float* __restrict__ W2,
                                                   const float* __restrict__ b2,
                                                   float* __restrict__ out_res,
                                                   float* __restrict__ out_attn) {
    __shared__ float w2_s[DM][DM];     // transposed: w2_s[e][d]
    __shared__ float res_s[8][DM];
    int tid = threadIdx.x;
    int slot = tid >> 5, d2 = tid & 31;
    int d = d2 * 2;
    for (int t = tid; t < DM*DM; t += 256) { int dd = t / DM, e = t % DM; w2_s[e][dd] = W2[t]; }
    __syncthreads();

    int bn = blockIdx.x * 8 + slot;
    const __half* lp = g_logit + (size_t)bn * KK * DM + d;
    const __half* vp = g_vpe + (size_t)bn * KK * DM + d;
    float* ao = out_attn + (size_t)bn * KK * DM + d;

    float2 v[KK];
    float m0 = -3.4e38f, m1 = -3.4e38f;
#pragma unroll
    for (int k = 0; k < KK; k++) {
        float2 t = __half22float2(*(const __half2*)(lp + k*DM));
        v[k] = t;
        m0 = fmaxf(m0, t.x); m1 = fmaxf(m1, t.y);
    }
    float s0 = 0.0f, s1 = 0.0f;
#pragma unroll
    for (int k = 0; k < KK; k++) {
        v[k].x = __expf(v[k].x - m0); s0 += v[k].x;
        v[k].y = __expf(v[k].y - m1); s1 += v[k].y;
    }
    float inv0 = 1.0f / s0, inv1 = 1.0f / s1;
    float a0 = 0.0f, a1 = 0.0f;
#pragma unroll
    for (int k = 0; k < KK; k++) {
        float p0 = v[k].x * inv0, p1 = v[k].y * inv1;
        float2 w = { p0, p1 };
        *(float2*)(ao + k*DM) = w;
        float2 fv = __half22float2(*(const __half2*)(vp + k*DM));
        a0 = fmaf(p0, fv.x, a0);
        a1 = fmaf(p1, fv.y, a1);
    }
    res_s[slot][d] = a0;
    res_s[slot][d+1] = a1;
    __syncthreads();

    float2 xv = *(const float2*)(g_x + (size_t)bn*DM + d);
    float o0 = b2[d] + xv.x;
    float o1 = b2[d+1] + xv.y;
#pragma unroll
    for (int e = 0; e < DM; e++) {
        float r = res_s[slot][e];
        o0 = fmaf(r, w2_s[e][d], o0);
        o1 = fmaf(r, w2_s[e][d+1], o1);
    }
    float2 ov = { o0, o1 };
    *(float2*)(out_res + (size_t)bn*DM + d) = ov;
}

extern "C" void kernel_launch(void* const* d_in, const int* in_sizes, int n_in,
                              void* d_out, int out_size) {
    const float* feat = (const float*)d_in[0];
    const float* xyz  = (const float*)d_in[1];
    const float* W1   = (const float*)d_in[2];
    const float* b1   = (const float*)d_in[3];
    const float* W2   = (const float*)d_in[4];
    const float* b2   = (const float*)d_in[5];
    const float* Wd1  = (const float*)d_in[6];
    const float* bd1  = (const float*)d_in[7];
    const float* Wd2  = (const float*)d_in[8];
    const float* bd2  = (const float*)d_in[9];
    const float* Wa   = (const float*)d_in[10];
    const float* ba   = (const float*)d_in[11];

    float* out_res  = (float*)d_out;
    float* out_attn = (float*)d_out + (size_t)BN * DM;

    cudaFuncSetAttribute(attn_gemm_mma, cudaFuncAttributeMaxDynamicSharedMemorySize, SMEM_GEMM);

    // fork-join: knn (xyz only) runs concurrently with prep on a side stream
    cudaStream_t s1;
    cudaStreamCreate(&s1);
    cudaEvent_t eFork, eJoin;
    cudaEventCreateWithFlags(&eFork, cudaEventDisableTiming);
    cudaEventCreateWithFlags(&eJoin, cudaEventDisableTiming);

    cudaEventRecord(eFork, 0);
    cudaStreamWaitEvent(s1, eFork, 0);
    dim3 kg(NN/KQW, BB);
    knn_kernel<<<kg, 512, 0, s1>>>(xyz);
    cudaEventRecord(eJoin, s1);

    prep_kernel<<<FC1_BLKS + WA_BLKS + WD_BLKS + BA_BLKS, 256>>>(feat, W1, b1, Wa, ba, Wd1, Wd2);

    cudaStreamWaitEvent(0, eJoin, 0);
    posenc_kernel<<<RR/POSB, 128>>>(xyz, bd1, bd2);
    dim3 gg(DK/TN, BN/TM);
    attn_gemm_mma<<<gg, 256, SMEM_GEMM>>>();
    softmax_out<<<BN/8, 256>>>(W2, b2, out_res, out_attn);

    cudaStreamDestroy(s1);      // deferred destroy; safe after join
    cudaEventDestroy(eFork);
    cudaEventDestroy(eJoin);
}